// round 2
// baseline (speedup 1.0000x reference)
#include <cuda_runtime.h>
#include <math.h>

#define N_  4096
#define D_  64
#define T_  60
#define H_  128
#define G_  512
#define NT_ 245760

__device__ float g_xg[(size_t)T_*N_*G_];
__device__ float g_gates[(size_t)N_*G_];
__device__ float g_h[N_*H_];
__device__ float g_c[N_*H_];
__device__ float g_hb[N_*H_];
__device__ float g_WpT[D_*G_];
__device__ float g_biasP[G_];
__device__ float g_WhhT[H_*G_];
__device__ float g_bn1sum[D_], g_bn1sq[D_];
__device__ float g_bn2sum[H_], g_bn2sq[H_];
__device__ float g_wa1[H_], g_wa2[H_], g_cc[2];
__device__ float g_s1[N_], g_s2[N_];
__device__ float g_s1s[N_];
__device__ int   g_perm[N_];
__device__ float g_e1[N_], g_e2[N_];
__device__ double g_P1[(size_t)(N_+1)*H_];
__device__ double g_P2[(size_t)(N_+1)*H_];
__device__ double g_D1[N_+1], g_D2[N_+1];
__device__ float g_M;

__device__ __forceinline__ float sigmoidf_(float v) { return 1.f/(1.f + expf(-v)); }

__global__ void k_init() {
    int idx = blockIdx.x*blockDim.x + threadIdx.x;
    if (idx < N_*H_) { g_h[idx] = 0.f; g_c[idx] = 0.f; }
    if (idx < D_)    { g_bn1sum[idx] = 0.f; g_bn1sq[idx] = 0.f; }
    if (idx < H_)    { g_bn2sum[idx] = 0.f; g_bn2sq[idx] = 0.f; }
}

__global__ void k_bn1(const float* __restrict__ x) {
    int d  = blockIdx.x;
    int n0 = blockIdx.y * 256;
    float s = 0.f, q = 0.f;
    for (int idx = threadIdx.x; idx < 256*T_; idx += 256) {
        int n = n0 + idx / T_;
        int t = idx - (idx / T_) * T_;
        float v = x[(size_t)n*(D_*T_) + d*T_ + t];
        s += v; q += v*v;
    }
    __shared__ float ss[256], qq[256];
    ss[threadIdx.x] = s; qq[threadIdx.x] = q;
    __syncthreads();
    for (int st = 128; st > 0; st >>= 1) {
        if (threadIdx.x < st) { ss[threadIdx.x] += ss[threadIdx.x+st]; qq[threadIdx.x] += qq[threadIdx.x+st]; }
        __syncthreads();
    }
    if (threadIdx.x == 0) { atomicAdd(&g_bn1sum[d], ss[0]); atomicAdd(&g_bn1sq[d], qq[0]); }
}

__global__ void k_prep(const float* __restrict__ bn1g, const float* __restrict__ bn1b,
                       const float* __restrict__ W_ih, const float* __restrict__ W_hh,
                       const float* __restrict__ b_ih, const float* __restrict__ b_hh,
                       const float* __restrict__ W_t,  const float* __restrict__ b_t,
                       const float* __restrict__ a) {
    __shared__ float sc[D_], sf[D_];
    int g = threadIdx.x;  // 512 threads
    if (g < D_) {
        float inv = 1.f / (float)NT_;
        float m   = g_bn1sum[g] * inv;
        float var = g_bn1sq[g]  * inv - m*m;
        float rs  = rsqrtf(var + 1e-5f);
        sc[g] = rs * bn1g[g];
        sf[g] = bn1b[g] - m * rs * bn1g[g];
    }
    __syncthreads();
    float b = b_ih[g] + b_hh[g];
    for (int d = 0; d < D_; ++d) {
        float w = W_ih[g*D_ + d];
        b += w * sf[d];
        g_WpT[d*G_ + g] = w * sc[d];
    }
    g_biasP[g] = b;
    for (int k = 0; k < H_; ++k) g_WhhT[k*G_ + g] = W_hh[g*H_ + k];
    if (g < H_) {
        float w1 = 0.f, w2 = 0.f;
        for (int h = 0; h < H_; ++h) { float wt = W_t[h*H_ + g]; w1 += wt*a[h]; w2 += wt*a[H_+h]; }
        g_wa1[g] = w1; g_wa2[g] = w2;
    }
    if (g == 0) {
        float c1 = 0.f, c2 = 0.f;
        for (int h = 0; h < H_; ++h) { c1 += b_t[h]*a[h]; c2 += b_t[h]*a[H_+h]; }
        g_cc[0] = c1; g_cc[1] = c2;
    }
}

// xg GEMM: [245760 x 64] @ [64 x 512], BN1 fused via W'
__global__ void k_xg(const float* __restrict__ x) {
    __shared__ float a_sh[64][64];    // [k][m]
    __shared__ float b_sh[64][128];   // [k][g]
    int tid = threadIdx.x;
    int r0  = blockIdx.x * 64;
    int g0  = blockIdx.y * 128;
    {
        int m  = tid & 63;
        int kh = tid >> 6;
        int r  = r0 + m;
        int n  = r / T_;
        int tt = r - n*T_;
        const float* xp = x + (size_t)n*(D_*T_) + tt;
        #pragma unroll
        for (int i = 0; i < 32; ++i) {
            int k = 2*i + kh;
            a_sh[k][m] = xp[(size_t)k*T_];
        }
    }
    #pragma unroll
    for (int i = 0; i < 16; ++i) {
        int idx4 = i*128 + tid;
        int kk = idx4 >> 5, gq = idx4 & 31;
        *(float4*)&b_sh[kk][gq*4] = *(const float4*)&g_WpT[(size_t)kk*G_ + g0 + gq*4];
    }
    __syncthreads();
    int cc = tid & 15, rr = tid >> 4;
    float acc[8][8];
    #pragma unroll
    for (int i = 0; i < 8; ++i)
        #pragma unroll
        for (int j = 0; j < 8; ++j) acc[i][j] = 0.f;
    #pragma unroll 8
    for (int k = 0; k < 64; ++k) {
        float4 b0 = *(float4*)&b_sh[k][cc*8];
        float4 b1 = *(float4*)&b_sh[k][cc*8 + 4];
        #pragma unroll
        for (int i = 0; i < 8; ++i) {
            float av = a_sh[k][rr*8 + i];
            acc[i][0] += av*b0.x; acc[i][1] += av*b0.y; acc[i][2] += av*b0.z; acc[i][3] += av*b0.w;
            acc[i][4] += av*b1.x; acc[i][5] += av*b1.y; acc[i][6] += av*b1.z; acc[i][7] += av*b1.w;
        }
    }
    float4 bb0 = *(const float4*)&g_biasP[g0 + cc*8];
    float4 bb1 = *(const float4*)&g_biasP[g0 + cc*8 + 4];
    #pragma unroll
    for (int i = 0; i < 8; ++i) {
        int r  = r0 + rr*8 + i;
        int n  = r / T_;
        int tt = r - n*T_;
        float* dst = g_xg + ((size_t)tt*N_ + n)*G_ + g0 + cc*8;
        float4 o0 = make_float4(acc[i][0]+bb0.x, acc[i][1]+bb0.y, acc[i][2]+bb0.z, acc[i][3]+bb0.w);
        float4 o1 = make_float4(acc[i][4]+bb1.x, acc[i][5]+bb1.y, acc[i][6]+bb1.z, acc[i][7]+bb1.w);
        *(float4*)&dst[0] = o0;
        *(float4*)&dst[4] = o1;
    }
}

// gates = xg[t] + h @ WhhT   (M=4096, N=512, K=128)
__global__ void k_gates(int tstep) {
    __shared__ float a_sh[64][64];    // [m][k]
    __shared__ float b_sh[64][128];   // [k][g]
    int tid = threadIdx.x;
    int n0  = blockIdx.x * 64;
    int g0  = blockIdx.y * 128;
    int cc  = tid & 15, rr = tid >> 4;
    float acc[8][8];
    #pragma unroll
    for (int i = 0; i < 8; ++i)
        #pragma unroll
        for (int j = 0; j < 8; ++j) acc[i][j] = 0.f;
    for (int kc = 0; kc < 2; ++kc) {
        #pragma unroll
        for (int i = 0; i < 8; ++i) {
            int idx4 = i*128 + tid;
            int row = idx4 >> 4, q = idx4 & 15;
            *(float4*)&a_sh[row][q*4] =
                *(const float4*)&g_h[(size_t)(n0+row)*H_ + kc*64 + q*4];
        }
        #pragma unroll
        for (int i = 0; i < 16; ++i) {
            int idx4 = i*128 + tid;
            int kk = idx4 >> 5, gq = idx4 & 31;
            *(float4*)&b_sh[kk][gq*4] =
                *(const float4*)&g_WhhT[(size_t)(kc*64+kk)*G_ + g0 + gq*4];
        }
        __syncthreads();
        #pragma unroll 8
        for (int k = 0; k < 64; ++k) {
            float4 b0 = *(float4*)&b_sh[k][cc*8];
            float4 b1 = *(float4*)&b_sh[k][cc*8 + 4];
            #pragma unroll
            for (int i = 0; i < 8; ++i) {
                float av = a_sh[rr*8 + i][k];
                acc[i][0] += av*b0.x; acc[i][1] += av*b0.y; acc[i][2] += av*b0.z; acc[i][3] += av*b0.w;
                acc[i][4] += av*b1.x; acc[i][5] += av*b1.y; acc[i][6] += av*b1.z; acc[i][7] += av*b1.w;
            }
        }
        __syncthreads();
    }
    const float* xgb = g_xg + (size_t)tstep*N_*G_;
    #pragma unroll
    for (int i = 0; i < 8; ++i) {
        int n = n0 + rr*8 + i;
        size_t off = (size_t)n*G_ + g0 + cc*8;
        float4 x0 = *(const float4*)&xgb[off];
        float4 x1 = *(const float4*)&xgb[off + 4];
        float4 o0 = make_float4(acc[i][0]+x0.x, acc[i][1]+x0.y, acc[i][2]+x0.z, acc[i][3]+x0.w);
        float4 o1 = make_float4(acc[i][4]+x1.x, acc[i][5]+x1.y, acc[i][6]+x1.z, acc[i][7]+x1.w);
        *(float4*)&g_gates[off]     = o0;
        *(float4*)&g_gates[off + 4] = o1;
    }
}

__global__ void k_cell() {
    int idx = blockIdx.x*blockDim.x + threadIdx.x;
    int n  = idx >> 7;
    int hh = idx & 127;
    const float* gr = g_gates + (size_t)n*G_;
    float ii = sigmoidf_(gr[hh]);
    float ff = sigmoidf_(gr[H_   + hh]);
    float gg = tanhf    (gr[2*H_ + hh]);
    float oo = sigmoidf_(gr[3*H_ + hh]);
    float c  = ff * g_c[idx] + ii * gg;
    g_c[idx] = c;
    g_h[idx] = oo * tanhf(c);
}

__global__ void k_bn2s() {
    int ch = threadIdx.x;
    int n0 = blockIdx.x * 32;
    float s = 0.f, q = 0.f;
    for (int r = 0; r < 32; ++r) { float v = g_h[(size_t)(n0+r)*H_ + ch]; s += v; q += v*v; }
    atomicAdd(&g_bn2sum[ch], s);
    atomicAdd(&g_bn2sq[ch],  q);
}

__global__ void k_bn2a(const float* __restrict__ g2, const float* __restrict__ b2) {
    int n = blockIdx.x, ch = threadIdx.x;
    float inv = 1.f / (float)N_;
    float m   = g_bn2sum[ch] * inv;
    float var = g_bn2sq[ch]  * inv - m*m;
    float hb  = (g_h[(size_t)n*H_ + ch] - m) * rsqrtf(var + 1e-5f) * g2[ch] + b2[ch];
    g_hb[(size_t)n*H_ + ch] = hb;
    __shared__ float r1[H_], r2[H_];
    r1[ch] = hb * g_wa1[ch];
    r2[ch] = hb * g_wa2[ch];
    __syncthreads();
    for (int s = 64; s > 0; s >>= 1) {
        if (ch < s) { r1[ch] += r1[ch+s]; r2[ch] += r2[ch+s]; }
        __syncthreads();
    }
    if (ch == 0) { g_s1[n] = r1[0] + g_cc[0]; g_s2[n] = r2[0] + g_cc[1]; }
}

__global__ void k_sort() {
    __shared__ float v[N_];
    __shared__ int   p[N_];
    int tid = threadIdx.x;
    for (int i = tid; i < N_; i += 1024) { v[i] = g_s1[i]; p[i] = i; }
    __syncthreads();
    for (int kk = 2; kk <= N_; kk <<= 1) {
        for (int j = kk >> 1; j > 0; j >>= 1) {
            for (int i = tid; i < N_; i += 1024) {
                int ixj = i ^ j;
                if (ixj > i) {
                    bool up = ((i & kk) == 0);   // descending overall
                    bool sw = up ? (v[i] < v[ixj]) : (v[i] > v[ixj]);
                    if (sw) {
                        float tv = v[i]; v[i] = v[ixj]; v[ixj] = tv;
                        int   tp = p[i]; p[i] = p[ixj]; p[ixj] = tp;
                    }
                }
            }
            __syncthreads();
        }
    }
    for (int i = tid; i < N_; i += 1024) { g_s1s[i] = v[i]; g_perm[i] = p[i]; }
}

__global__ void k_exp() {
    int i = blockIdx.x*blockDim.x + threadIdx.x;
    float M = g_s1s[0];
    if (i == 0) g_M = M;
    if (i < N_) {
        g_e1[i] = expf(g_s1s[i] - M);
        g_e2[i] = expf(0.01f * g_s1s[i]);
    }
}

// per-channel prefix sums of e1*hb and e2*hb over sorted order
__global__ void k_prefix_ch() {
    int ch  = blockIdx.x;
    int tid = threadIdx.x;   // 256
    __shared__ double tsum[256];
    int base = tid * 16;
    // pass 1: e1
    {
        double loc[16]; double s = 0.0;
        #pragma unroll
        for (int i = 0; i < 16; ++i) {
            int j = base + i;
            s += (double)g_e1[j] * (double)g_hb[(size_t)g_perm[j]*H_ + ch];
            loc[i] = s;
        }
        tsum[tid] = s; __syncthreads();
        for (int off = 1; off < 256; off <<= 1) {
            double vv = (tid >= off) ? tsum[tid-off] : 0.0;
            __syncthreads();
            tsum[tid] += vv;
            __syncthreads();
        }
        double excl = tsum[tid] - s;
        if (tid == 0) g_P1[ch] = 0.0;
        #pragma unroll
        for (int i = 0; i < 16; ++i) g_P1[(size_t)(base+i+1)*H_ + ch] = excl + loc[i];
    }
    __syncthreads();
    // pass 2: e2
    {
        double loc[16]; double s = 0.0;
        #pragma unroll
        for (int i = 0; i < 16; ++i) {
            int j = base + i;
            s += (double)g_e2[j] * (double)g_hb[(size_t)g_perm[j]*H_ + ch];
            loc[i] = s;
        }
        tsum[tid] = s; __syncthreads();
        for (int off = 1; off < 256; off <<= 1) {
            double vv = (tid >= off) ? tsum[tid-off] : 0.0;
            __syncthreads();
            tsum[tid] += vv;
            __syncthreads();
        }
        double excl = tsum[tid] - s;
        if (tid == 0) g_P2[ch] = 0.0;
        #pragma unroll
        for (int i = 0; i < 16; ++i) g_P2[(size_t)(base+i+1)*H_ + ch] = excl + loc[i];
    }
}

__global__ void k_prefix_scalar() {
    int tid = threadIdx.x;   // 256
    __shared__ double tsum[256];
    int base = tid * 16;
    for (int pass = 0; pass < 2; ++pass) {
        const float* e = pass ? g_e2 : g_e1;
        double* P = pass ? g_D2 : g_D1;
        double loc[16]; double s = 0.0;
        #pragma unroll
        for (int i = 0; i < 16; ++i) { s += (double)e[base+i]; loc[i] = s; }
        tsum[tid] = s; __syncthreads();
        for (int off = 1; off < 256; off <<= 1) {
            double vv = (tid >= off) ? tsum[tid-off] : 0.0;
            __syncthreads();
            tsum[tid] += vv;
            __syncthreads();
        }
        double excl = tsum[tid] - s;
        if (tid == 0) P[0] = 0.0;
        #pragma unroll
        for (int i = 0; i < 16; ++i) P[base+i+1] = excl + loc[i];
        __syncthreads();
    }
}

// per-row: softmax via prefix tables, +residual, FC, output head
__global__ void k_att(float* __restrict__ out,
                      const float* __restrict__ Wfc, const float* __restrict__ bfc,
                      const float* __restrict__ Wout, const float* __restrict__ bout) {
    int i   = blockIdx.x;
    int tid = threadIdx.x;   // 128
    __shared__ float h2s[H_];
    __shared__ float red[H_];
    __shared__ int   ksh;
    float s2i = g_s2[i];
    if (tid == 0) {
        float thr = -s2i;
        int lo = 0, hi = N_;           // first idx with s1s < thr (descending array)
        while (lo < hi) { int mid = (lo+hi) >> 1; if (g_s1s[mid] >= thr) lo = mid+1; else hi = mid; }
        ksh = lo;
    }
    __syncthreads();
    int k = ksh;
    double f1 = exp((double)s2i + (double)g_M);
    double f2 = exp(0.01 * (double)s2i);
    double den = f1 * g_D1[k] + f2 * (g_D2[N_] - g_D2[k]);
    double num = f1 * g_P1[(size_t)k*H_ + tid]
               + f2 * (g_P2[(size_t)N_*H_ + tid] - g_P2[(size_t)k*H_ + tid]);
    h2s[tid] = (float)(num / den) + g_hb[(size_t)i*H_ + tid];
    __syncthreads();
    float acc = bfc[tid];
    #pragma unroll 8
    for (int ch = 0; ch < H_; ++ch) acc += Wfc[tid*H_ + ch] * h2s[ch];
    float h3 = acc >= 0.f ? acc : 0.01f * acc;
    red[tid] = h3 * Wout[tid];
    __syncthreads();
    for (int s = 64; s > 0; s >>= 1) {
        if (tid < s) red[tid] += red[tid + s];
        __syncthreads();
    }
    if (tid == 0) out[i] = sigmoidf_(red[0] + bout[0]);
}

extern "C" void kernel_launch(void* const* d_in, const int* in_sizes, int n_in,
                              void* d_out, int out_size) {
    const float* x     = (const float*)d_in[0];
    const float* bn1g  = (const float*)d_in[1];
    const float* bn1b  = (const float*)d_in[2];
    const float* W_ih  = (const float*)d_in[3];
    const float* W_hh  = (const float*)d_in[4];
    const float* b_ih  = (const float*)d_in[5];
    const float* b_hh  = (const float*)d_in[6];
    const float* bn2g  = (const float*)d_in[7];
    const float* bn2b  = (const float*)d_in[8];
    const float* W_t   = (const float*)d_in[9];
    const float* b_t   = (const float*)d_in[10];
    const float* a     = (const float*)d_in[11];
    const float* W_fc  = (const float*)d_in[12];
    const float* b_fc  = (const float*)d_in[13];
    const float* W_out = (const float*)d_in[14];
    const float* b_out = (const float*)d_in[15];
    float* out = (float*)d_out;

    k_init<<<(N_*H_+255)/256, 256>>>();
    k_bn1<<<dim3(D_, 16), 256>>>(x);
    k_prep<<<1, 512>>>(bn1g, bn1b, W_ih, W_hh, b_ih, b_hh, W_t, b_t, a);
    k_xg<<<dim3(NT_/64, 4), 128>>>(x);
    for (int t = 0; t < T_; ++t) {
        k_gates<<<dim3(N_/64, 4), 128>>>(t);
        k_cell<<<(N_*H_)/256, 256>>>();
    }
    k_bn2s<<<N_/32, 128>>>();
    k_bn2a<<<N_, 128>>>(bn2g, bn2b);
    k_sort<<<1, 1024>>>();
    k_exp<<<(N_+255)/256, 256>>>();
    k_prefix_ch<<<H_, 256>>>();
    k_prefix_scalar<<<1, 256>>>();
    k_att<<<N_, 128>>>(out, W_fc, b_fc, W_out, b_out);
}